// round 2
// baseline (speedup 1.0000x reference)
#include <cuda_runtime.h>
#include <cstdint>
#include <math.h>

#define BB   16
#define CIN  64
#define HH   64
#define WW   64
#define HID  128
#define OC4  512   // 4*HID

// scratch for z_is: [b][h][oc][w]
__device__ float g_z[BB * HH * OC4 * WW];
// double-buffered h state: [par][b][ic][w]
__device__ float g_h[2 * BB * HID * WW];
// progress flags: [b][rank]
__device__ int   g_flag[BB * 8];

// ----------------------------------------------------------------------------
// Kernel 0: zero h parity-0 buffer and flags (graph-replay safe init)
// ----------------------------------------------------------------------------
__global__ void init_kernel()
{
    int i = blockIdx.x * 256 + threadIdx.x;
    if (i < BB * HID * WW) g_h[i] = 0.f;          // parity 0 only
    if (i < BB * 8)        g_flag[i] = 0;
}

// ----------------------------------------------------------------------------
// Kernel 1: masked input conv (taps 0,1 of the 1x3 kernel)
// z[b,h,oc,w] = b_is[oc] + sum_cin ( x[b,cin,h,w-1]*w_is[oc,cin,0]
//                                  + x[b,cin,h,w  ]*w_is[oc,cin,1] )
// grid = B*H blocks, 256 threads. smem: xs[64][68] + ws[64][2][128]
// ----------------------------------------------------------------------------
__global__ void __launch_bounds__(256)
conv_in_kernel(const float* __restrict__ x,
               const float* __restrict__ w_is,
               const float* __restrict__ b_is)
{
    extern __shared__ float smem[];
    float* xs = smem;              // [cin][68], xs[cin][w+1] = x, pads zero
    float* ws = smem + 64 * 68;    // [cin][t(2)][ocl(128)]

    int tid = threadIdx.x;
    int bh  = blockIdx.x;
    int b   = bh >> 6;
    int h   = bh & 63;

    const float* xb = x + ((long)(b * CIN) * HH + h) * WW;
    for (int i = tid; i < CIN * WW; i += 256) {
        int cin = i >> 6, w = i & 63;
        xs[cin * 68 + w + 1] = xb[(long)cin * HH * WW + w];
    }
    if (tid < 64) {
        xs[tid * 68 + 0]  = 0.f;
        xs[tid * 68 + 65] = 0.f;
        xs[tid * 68 + 66] = 0.f;
        xs[tid * 68 + 67] = 0.f;
    }
    __syncthreads();

    int wb  = tid & 3;        // w-block of 16
    int ocl = tid >> 2;       // 0..63
    int w0  = wb * 16;

    for (int p = 0; p < 4; p++) {
        int ocbase = p * 128;
        for (int i = tid; i < 128 * 192; i += 256) {
            int ol = i / 192, r = i % 192;
            int cin = r / 3, t = r % 3;
            float v = w_is[(long)(ocbase + ol) * 192 + r];
            if (t < 2) ws[(cin * 2 + t) * 128 + ol] = v;
        }
        __syncthreads();

        float acc0[16], acc1[16];
        float bb0 = b_is[ocbase + ocl];
        float bb1 = b_is[ocbase + ocl + 64];
#pragma unroll
        for (int j = 0; j < 16; j++) { acc0[j] = bb0; acc1[j] = bb1; }

        for (int cin = 0; cin < 64; cin++) {
            float w00 = ws[(cin * 2 + 0) * 128 + ocl];
            float w01 = ws[(cin * 2 + 1) * 128 + ocl];
            float w10 = ws[(cin * 2 + 0) * 128 + ocl + 64];
            float w11 = ws[(cin * 2 + 1) * 128 + ocl + 64];
            float xv[20];
            const float4* xp = reinterpret_cast<const float4*>(&xs[cin * 68 + w0]);
            *(float4*)&xv[0]  = xp[0];
            *(float4*)&xv[4]  = xp[1];
            *(float4*)&xv[8]  = xp[2];
            *(float4*)&xv[12] = xp[3];
            *(float4*)&xv[16] = xp[4];
#pragma unroll
            for (int j = 0; j < 16; j++) {
                acc0[j] = fmaf(xv[j],     w00, acc0[j]);
                acc0[j] = fmaf(xv[j + 1], w01, acc0[j]);
                acc1[j] = fmaf(xv[j],     w10, acc1[j]);
                acc1[j] = fmaf(xv[j + 1], w11, acc1[j]);
            }
        }

        float* z0 = &g_z[((long)bh * OC4 + ocbase + ocl)      * WW + w0];
        float* z1 = &g_z[((long)bh * OC4 + ocbase + ocl + 64) * WW + w0];
#pragma unroll
        for (int j = 0; j < 16; j++) { z0[j] = acc0[j]; z1[j] = acc1[j]; }
        __syncthreads();
    }
}

// ----------------------------------------------------------------------------
// Kernel 2: sequential row scan. 8 CTAs per batch (no clusters).
// CTA rank r owns hidden channels [16r, 16r+16) and all 4 gates for them.
// h exchanged through double-buffered global memory + flag sync.
// Grid = 128 CTAs at 1 CTA/SM -> single wave, all co-resident.
// ----------------------------------------------------------------------------
__global__ void __launch_bounds__(256)
scan_kernel(const float* __restrict__ w_ss,
            const float* __restrict__ b_ss,
            float* __restrict__ out)
{
    extern __shared__ float smem[];
    float* Wsm  = smem;                    // [(ic*3+t)][64 l]   24576 floats
    float* hs   = Wsm + 128 * 3 * 64;      // [128 ic][68]        8704 floats
    float* zbuf = hs + 128 * 68;           // [64 l][64 w]        4096 floats
    float* cs   = zbuf + 64 * 64;          // [16 hcl][64 w]      1024 floats
    float* bsm  = cs + 16 * 64;            // [64 l]

    int tid  = threadIdx.x;
    int rank = blockIdx.x & 7;
    int b    = blockIdx.x >> 3;

    // stage recurrent weights: Wsm[(ic*3+t)*64 + l] = w_ss[ocg][ic][t]
    for (int i = tid; i < 128 * 3 * 64; i += 256) {
        int ic = i / 192, r = i % 192;
        int t = r >> 6, l = r & 63;
        int ocg = (l >> 4) * 128 + rank * 16 + (l & 15);
        Wsm[(ic * 3 + t) * 64 + l] = w_ss[((long)ocg * 128 + ic) * 3 + t];
    }
    if (tid < 64) {
        int l = tid;
        int ocg = (l >> 4) * 128 + rank * 16 + (l & 15);
        bsm[l] = b_ss[ocg];
    }
    // zero h pads (persist across rows) and c state
    for (int i = tid; i < 128; i += 256) {
        hs[i * 68 + 0]  = 0.f;
        hs[i * 68 + 65] = 0.f;
        hs[i * 68 + 66] = 0.f;
        hs[i * 68 + 67] = 0.f;
    }
    for (int i = tid; i < 16 * 64; i += 256) cs[i] = 0.f;
    __syncthreads();

    int wb = tid & 3;
    int l  = tid >> 2;        // 0..63: gate g = l>>4, local hid = l&15
    int w0 = wb * 16;
    int ocg = (l >> 4) * 128 + rank * 16 + (l & 15);
    float bias = bsm[l];

    volatile int* flags = g_flag + b * 8;

    for (int row = 0; row < HH; row++) {
        int par  = row & 1;
        int par1 = par ^ 1;

        // load full h (parity par) into padded smem
        const float4* gh4 = (const float4*)&g_h[((long)par * BB + b) * HID * WW];
        for (int i = tid; i < 2048; i += 256) {        // float4 index
            int ic = i >> 4, w = (i & 15) * 4;
            float4 v = gh4[i];
            float* d = &hs[ic * 68 + w + 1];
            d[0] = v.x; d[1] = v.y; d[2] = v.z; d[3] = v.w;
        }
        __syncthreads();

        // acc = z_is + bias
        const float* zg = &g_z[(((long)b * HH + row) * OC4 + ocg) * WW + w0];
        float acc[16];
#pragma unroll
        for (int j4 = 0; j4 < 4; j4++) {
            float4 v = *(const float4*)&zg[j4 * 4];
            acc[j4 * 4 + 0] = v.x + bias;
            acc[j4 * 4 + 1] = v.y + bias;
            acc[j4 * 4 + 2] = v.z + bias;
            acc[j4 * 4 + 3] = v.w + bias;
        }
        // recurrent conv: acc[j] += sum_ic,t h[ic][w0+j+t-1]*W[l][ic][t]
        for (int ic = 0; ic < 128; ic++) {
            float wt0 = Wsm[(ic * 3 + 0) * 64 + l];
            float wt1 = Wsm[(ic * 3 + 1) * 64 + l];
            float wt2 = Wsm[(ic * 3 + 2) * 64 + l];
            float hv[20];
            const float4* hp = (const float4*)&hs[ic * 68 + w0];
            *(float4*)&hv[0]  = hp[0];
            *(float4*)&hv[4]  = hp[1];
            *(float4*)&hv[8]  = hp[2];
            *(float4*)&hv[12] = hp[3];
            *(float4*)&hv[16] = hp[4];
#pragma unroll
            for (int j = 0; j < 16; j++) {
                acc[j] = fmaf(hv[j],     wt0, acc[j]);
                acc[j] = fmaf(hv[j + 1], wt1, acc[j]);
                acc[j] = fmaf(hv[j + 2], wt2, acc[j]);
            }
        }
#pragma unroll
        for (int j = 0; j < 16; j++) zbuf[l * 64 + w0 + j] = acc[j];
        __syncthreads();

        // gate math: 1024 (hcl,w) elems, 4 per thread; write out + new h
        float* ghw = &g_h[((long)par1 * BB + b) * HID * WW];
#pragma unroll
        for (int k = 0; k < 4; k++) {
            int idx = tid + k * 256;
            int hcl = idx >> 6, w = idx & 63;
            float zi  = zbuf[(0  + hcl) * 64 + w];
            float zf  = zbuf[(16 + hcl) * 64 + w];
            float zo  = zbuf[(32 + hcl) * 64 + w];
            float zg2 = zbuf[(48 + hcl) * 64 + w];
            float ig = 1.f / (1.f + expf(-zi));
            float fg = 1.f / (1.f + expf(-zf));
            float og = 1.f / (1.f + expf(-zo));
            float gg = tanhf(zg2);
            float c = fg * cs[hcl * 64 + w] + ig * gg;
            cs[hcl * 64 + w] = c;
            float hv2 = og * tanhf(c);
            int ch = rank * 16 + hcl;
            out[(((long)b * HID + ch) * HH + row) * WW + w] = hv2;
            if (row < HH - 1) ghw[ch * WW + w] = hv2;
        }

        if (row < HH - 1) {
            // publish: fence + flag, then wait for all 8 ranks
            __threadfence();
            __syncthreads();
            if (tid == 0) flags[rank] = row + 1;
            if (tid < 8) {
                while (flags[tid] < row + 1) __nanosleep(40);
            }
            __threadfence();
            __syncthreads();
        }
    }
}

// ----------------------------------------------------------------------------
extern "C" void kernel_launch(void* const* d_in, const int* in_sizes, int n_in,
                              void* d_out, int out_size)
{
    (void)in_sizes; (void)n_in; (void)out_size;
    const float* x    = (const float*)d_in[0];
    const float* w_is = (const float*)d_in[1];
    const float* b_is = (const float*)d_in[2];
    const float* w_ss = (const float*)d_in[3];
    const float* b_ss = (const float*)d_in[4];
    float* out = (float*)d_out;

    const int conv_smem = (64 * 68 + 64 * 2 * 128) * 4;                           // 82944 B
    const int scan_smem = (128 * 3 * 64 + 128 * 68 + 64 * 64 + 16 * 64 + 64) * 4; // 153856 B

    cudaFuncSetAttribute(conv_in_kernel, cudaFuncAttributeMaxDynamicSharedMemorySize, conv_smem);
    cudaFuncSetAttribute(scan_kernel,    cudaFuncAttributeMaxDynamicSharedMemorySize, scan_smem);

    init_kernel<<<(BB * HID * WW + 255) / 256, 256>>>();
    conv_in_kernel<<<BB * HH, 256, conv_smem>>>(x, w_is, b_is);
    scan_kernel<<<BB * 8, 256, scan_smem>>>(w_ss, b_ss, out);
}